// round 1
// baseline (speedup 1.0000x reference)
#include <cuda_runtime.h>
#include <math.h>

#define N_   512
#define M_   2048
#define C_   256
#define KTOP 6

// Scratch (static __device__ globals: allocation-free per harness rules)
__device__ float g_bw[N_ * C_];
__device__ float g_Aq[M_];
__device__ float g_Bq[N_];
__device__ float g_anti[N_ * M_];
__device__ float g_rowco[N_];

// ---------------------------------------------------------------------------
// Kernel 1: per-row weighted squared norms + weighted micro rows.
//   blocks [0, M_)          -> Aq[m] = sum_c w'[c] * a[m,c]^2
//   blocks [M_, M_+N_)      -> Bq[n] = sum_c w'[c] * b[n,c]^2 ; bw = w'*b
// w'[c] = fc_w[c] - 1/C  (folds the dis.mean(axis=2) term into the weight)
// ---------------------------------------------------------------------------
__global__ void prep_kernel(const float* __restrict__ micro,
                            const float* __restrict__ micro_all,
                            const float* __restrict__ fc_w) {
    const float invC = 1.0f / (float)C_;
    int c = threadIdx.x;                 // 256 threads = C_
    int b = blockIdx.x;
    float wp = fc_w[c] - invC;

    __shared__ float red[C_];
    float t;
    if (b < M_) {
        float v = micro_all[b * C_ + c];
        t = wp * v * v;
    } else {
        int n = b - M_;
        float v = micro[n * C_ + c];
        g_bw[n * C_ + c] = wp * v;
        t = wp * v * v;
    }
    red[c] = t;
    __syncthreads();
    #pragma unroll
    for (int s = C_ / 2; s > 0; s >>= 1) {
        if (c < s) red[c] += red[c + s];
        __syncthreads();
    }
    if (c == 0) {
        if (b < M_) g_Aq[b] = red[0];
        else        g_Bq[b - M_] = red[0];
    }
}

// ---------------------------------------------------------------------------
// Kernel 2: anti[n,m] = Bq[n] + Aq[m] - 2 * dot(bw[n,:], a[m,:])
// Classic SIMT fp32 tiled GEMM (NT): 64x64 tile, K-chunk 16, 4x4 per thread.
// ---------------------------------------------------------------------------
#define BM 64
#define BN 64
#define BK 16

__global__ void __launch_bounds__(256, 4) anti_gemm(const float* __restrict__ micro_all) {
    __shared__ float As[BK][BM + 4];   // As[k][n_local] (pad keeps 16B align)
    __shared__ float Bs[BK][BN + 4];   // Bs[k][m_local]

    int tid = threadIdx.x;
    int tx = tid & 15;          // m direction (16)
    int ty = tid >> 4;          // n direction (16)
    int m0 = blockIdx.x * BN;
    int n0 = blockIdx.y * BM;

    int lr = tid >> 2;          // 0..63 row within tile
    int lk = (tid & 3) << 2;    // 0,4,8,12 k-subgroup

    float acc[4][4] = {};

    for (int k0 = 0; k0 < C_; k0 += BK) {
        float4 av = *(const float4*)&g_bw[(n0 + lr) * C_ + k0 + lk];
        float4 bv = *(const float4*)&micro_all[(m0 + lr) * C_ + k0 + lk];
        As[lk + 0][lr] = av.x; As[lk + 1][lr] = av.y;
        As[lk + 2][lr] = av.z; As[lk + 3][lr] = av.w;
        Bs[lk + 0][lr] = bv.x; Bs[lk + 1][lr] = bv.y;
        Bs[lk + 2][lr] = bv.z; Bs[lk + 3][lr] = bv.w;
        __syncthreads();

        #pragma unroll
        for (int k = 0; k < BK; k++) {
            float4 af = *(const float4*)&As[k][ty << 2];
            float4 bf = *(const float4*)&Bs[k][tx << 2];
            float a[4] = {af.x, af.y, af.z, af.w};
            float bb[4] = {bf.x, bf.y, bf.z, bf.w};
            #pragma unroll
            for (int i = 0; i < 4; i++)
                #pragma unroll
                for (int j = 0; j < 4; j++)
                    acc[i][j] += a[i] * bb[j];
        }
        __syncthreads();
    }

    #pragma unroll
    for (int i = 0; i < 4; i++) {
        int n = n0 + (ty << 2) + i;
        float bq = g_Bq[n];
        #pragma unroll
        for (int j = 0; j < 4; j++) {
            int m = m0 + (tx << 2) + j;
            g_anti[n * M_ + m] = bq + g_Aq[m] - 2.0f * acc[i][j];
        }
    }
}

// ---------------------------------------------------------------------------
// Kernel 3: per-row top-6 (exact lax.top_k semantics: largest values, ties ->
// lowest index), exp-renormalized weights over top-6 (softmax denominator
// cancels analytically), fused output row + per-row co_loss partial.
// ---------------------------------------------------------------------------
__global__ void topk_kernel(const float* __restrict__ micro,
                            const float* __restrict__ micro_all,
                            const float* __restrict__ label,
                            const float* __restrict__ label_all,
                            float* __restrict__ out) {
    int n = blockIdx.x;
    int tid = threadIdx.x;            // 256 threads

    __shared__ float srow[M_];
    __shared__ float rv[256];
    __shared__ int   ri[256];
    __shared__ int   sidx[KTOP];
    __shared__ float scut[KTOP];      // selected values, later cut weights

    #pragma unroll
    for (int j = 0; j < M_ / 256; j++)
        srow[tid + j * 256] = g_anti[n * M_ + tid + j * 256];
    __syncthreads();

    for (int it = 0; it < KTOP; it++) {
        float best = -INFINITY;
        int bi = M_;
        #pragma unroll
        for (int j = 0; j < M_ / 256; j++) {
            int idx = tid + j * 256;
            float v = srow[idx];
            if (v > best || (v == best && idx < bi)) { best = v; bi = idx; }
        }
        rv[tid] = best; ri[tid] = bi;
        __syncthreads();
        #pragma unroll
        for (int s = 128; s > 0; s >>= 1) {
            if (tid < s) {
                float v2 = rv[tid + s]; int i2 = ri[tid + s];
                if (v2 > rv[tid] || (v2 == rv[tid] && i2 < ri[tid])) {
                    rv[tid] = v2; ri[tid] = i2;
                }
            }
            __syncthreads();
        }
        if (tid == 0) {
            sidx[it] = ri[0];
            scut[it] = rv[0];
            srow[ri[0]] = -INFINITY;   // exclude for next pass
        }
        __syncthreads();
    }

    if (tid == 0) {
        float vmax = scut[0];          // first selected == row max
        float e[KTOP];
        float s = 0.0f;
        #pragma unroll
        for (int k = 0; k < KTOP; k++) { e[k] = expf(scut[k] - vmax); s += e[k]; }
        float lab = label[n];
        float co = 0.0f;
        #pragma unroll
        for (int k = 0; k < KTOP; k++) {
            float ck = e[k] / s;
            scut[k] = ck;
            co += ck * fabsf(label_all[sidx[k]] - lab);
        }
        g_rowco[n] = co;
    }
    __syncthreads();

    // micro_tmp[n, c] = micro[n, c] + sum_k cut_k * micro_all[idx_k, c]
    float o = micro[n * C_ + tid];
    #pragma unroll
    for (int k = 0; k < KTOP; k++)
        o += scut[k] * micro_all[sidx[k] * C_ + tid];
    out[n * C_ + tid] = o;
}

// ---------------------------------------------------------------------------
// Kernel 4: deterministic co_loss reduction (fixed-order tree; no atomics).
// ---------------------------------------------------------------------------
__global__ void coloss_kernel(float* __restrict__ out, int out_size) {
    __shared__ float red[N_];
    int t = threadIdx.x;               // 512 threads
    red[t] = g_rowco[t];
    __syncthreads();
    #pragma unroll
    for (int s = N_ / 2; s > 0; s >>= 1) {
        if (t < s) red[t] += red[t + s];
        __syncthreads();
    }
    if (t == 0 && out_size > N_ * C_)
        out[N_ * C_] = 1e-4f + red[0] / (float)N_;
}

// ---------------------------------------------------------------------------
extern "C" void kernel_launch(void* const* d_in, const int* in_sizes, int n_in,
                              void* d_out, int out_size) {
    const float* micro     = (const float*)d_in[0];   // [512, 256]
    const float* label     = (const float*)d_in[1];   // [512]
    const float* micro_all = (const float*)d_in[2];   // [2048, 256]
    const float* label_all = (const float*)d_in[3];   // [2048]
    const float* fc_w      = (const float*)d_in[4];   // [256]
    float* out = (float*)d_out;

    prep_kernel<<<M_ + N_, C_>>>(micro, micro_all, fc_w);
    dim3 g(M_ / BN, N_ / BM);
    anti_gemm<<<g, 256>>>(micro_all);
    topk_kernel<<<N_, C_>>>(micro, micro_all, label, label_all, out);
    coloss_kernel<<<1, N_>>>(out, out_size);
}

// round 2
// speedup vs baseline: 1.3489x; 1.3489x over previous
#include <cuda_runtime.h>
#include <math.h>

#define N_   512
#define M_   2048
#define C_   256
#define KTOP 6

typedef unsigned long long ull;

// Scratch (static __device__ globals: allocation-free per harness rules)
__device__ float g_anti[N_ * M_];
__device__ float g_rowco[N_];
__device__ int   g_cnt = 0;

// ---- packed f32x2 helpers (FFMA2: 2 FMA per instruction on sm_103a) -------
__device__ __forceinline__ ull pack2(float x) {
    ull r; asm("mov.b64 %0, {%1, %1};" : "=l"(r) : "f"(x)); return r;
}
__device__ __forceinline__ void fma2(ull& d, ull a, ull b) {
    asm("fma.rn.f32x2 %0, %1, %2, %0;" : "+l"(d) : "l"(a), "l"(b));
}
__device__ __forceinline__ void unpack2(ull v, float& lo, float& hi) {
    asm("mov.b64 {%0, %1}, %2;" : "=f"(lo), "=f"(hi) : "l"(v));
}

// ---------------------------------------------------------------------------
// Kernel 1 (fused): anti[n,m] = Aq[m] - 2 * dot(w'*micro[n], micro_all[m])
//   w'[c] = fc_w[c] - 1/C   (folds dis.mean into weight)
//   Aq[m] = sum_c w'[c]*micro_all[m,c]^2    (computed inline by the B loader)
//   (the per-row Bq[n] term is dropped: constant per row -> invariant for
//    top-k selection and for exp(anti - rowmax) weights)
// Tile: 128(m) x 64(n), 128 threads, 8x8 per-thread frag, BK=16, double-buf.
// grid (16, 8) = 128 blocks = one wave on 148 SMs.
// ---------------------------------------------------------------------------
#define TM 128
#define TN 64
#define TK 16

__global__ void __launch_bounds__(128, 1)
anti_gemm(const float* __restrict__ micro,
          const float* __restrict__ micro_all,
          const float* __restrict__ fc_w) {
    __shared__ float As[2][TK][TN + 4];     // As[k][n] = w'[k]*micro[n,k]
    __shared__ float Bs[2][TK][TM + 4];     // Bs[k][m] = micro_all[m,k]
    __shared__ float sw[C_];                // w'
    __shared__ float sAqP[512];             // Aq partials: [m_local*4 + kgrp]

    const int tid = threadIdx.x;
    const int m0 = blockIdx.x * TM;
    const int n0 = blockIdx.y * TN;

    const float invC = 1.0f / (float)C_;
    sw[tid]       = fc_w[tid]       - invC;
    sw[tid + 128] = fc_w[tid + 128] - invC;
    __syncthreads();

    const int lr  = tid >> 2;           // 0..31 (base row of loader slots)
    const int lkp = (tid & 3) << 2;     // k sub-offset 0,4,8,12
    const int tx  = tid & 15;           // m frag group
    const int ty  = tid >> 4;           // n frag group

    float4 pb[4], pa[2];
    float  aqp[4] = {0.f, 0.f, 0.f, 0.f};
    ull    acc[8][4];
    #pragma unroll
    for (int i = 0; i < 8; i++)
        #pragma unroll
        for (int j = 0; j < 4; j++) acc[i][j] = 0ull;  // bits of (0.f,0.f)

    // global-load prefetch of one K-chunk into registers
    auto LOAD = [&](int k0) {
        #pragma unroll
        for (int i = 0; i < 4; i++)
            pb[i] = *(const float4*)&micro_all[(m0 + lr + 32 * i) * C_ + k0 + lkp];
        #pragma unroll
        for (int i = 0; i < 2; i++)
            pa[i] = *(const float4*)&micro[(n0 + lr + 32 * i) * C_ + k0 + lkp];
    };
    // regs -> smem (also accumulates Aq partials while data is in registers)
    auto STORE = [&](int buf, int k0) {
        float4 w4 = *(const float4*)&sw[k0 + lkp];
        #pragma unroll
        for (int i = 0; i < 4; i++) {
            int r = lr + 32 * i;
            Bs[buf][lkp + 0][r] = pb[i].x;
            Bs[buf][lkp + 1][r] = pb[i].y;
            Bs[buf][lkp + 2][r] = pb[i].z;
            Bs[buf][lkp + 3][r] = pb[i].w;
            aqp[i] += w4.x * pb[i].x * pb[i].x + w4.y * pb[i].y * pb[i].y
                    + w4.z * pb[i].z * pb[i].z + w4.w * pb[i].w * pb[i].w;
        }
        #pragma unroll
        for (int i = 0; i < 2; i++) {
            int r = lr + 32 * i;
            As[buf][lkp + 0][r] = w4.x * pa[i].x;
            As[buf][lkp + 1][r] = w4.y * pa[i].y;
            As[buf][lkp + 2][r] = w4.z * pa[i].z;
            As[buf][lkp + 3][r] = w4.w * pa[i].w;
        }
    };

    LOAD(0);
    STORE(0, 0);
    __syncthreads();

    #pragma unroll 1
    for (int c = 0; c < C_ / TK; c++) {
        if (c < C_ / TK - 1) LOAD((c + 1) * TK);
        const int buf = c & 1;
        #pragma unroll
        for (int k = 0; k < TK; k++) {
            float4 a0 = *(const float4*)&As[buf][k][ty * 8];
            float4 a1 = *(const float4*)&As[buf][k][ty * 8 + 4];
            ulonglong2 b0 = *(const ulonglong2*)&Bs[buf][k][tx * 8];
            ulonglong2 b1 = *(const ulonglong2*)&Bs[buf][k][tx * 8 + 4];
            ull bb0 = b0.x, bb1 = b0.y, bb2 = b1.x, bb3 = b1.y;
            float av[8] = {a0.x, a0.y, a0.z, a0.w, a1.x, a1.y, a1.z, a1.w};
            #pragma unroll
            for (int i = 0; i < 8; i++) {
                ull aa = pack2(av[i]);
                fma2(acc[i][0], aa, bb0);
                fma2(acc[i][1], aa, bb1);
                fma2(acc[i][2], aa, bb2);
                fma2(acc[i][3], aa, bb3);
            }
        }
        if (c < C_ / TK - 1) {
            STORE((c + 1) & 1, (c + 1) * TK);
            __syncthreads();
        }
    }

    // publish Aq partials: slot idx = tid + 128*i  <->  m_local*4 + kgrp
    #pragma unroll
    for (int i = 0; i < 4; i++) sAqP[tid + 128 * i] = aqp[i];
    __syncthreads();

    // per-thread Aq for its 8 m columns (fixed-order 4-way sums)
    float aqv[8];
    #pragma unroll
    for (int t = 0; t < 8; t++) {
        float4 q = *(const float4*)&sAqP[(tx * 8 + t) * 4];
        aqv[t] = (q.x + q.y) + (q.z + q.w);
    }

    #pragma unroll
    for (int i = 0; i < 8; i++) {
        int n = n0 + ty * 8 + i;
        float lo0, hi0, lo1, hi1;
        unpack2(acc[i][0], lo0, hi0);
        unpack2(acc[i][1], lo1, hi1);
        float4 o0 = make_float4(aqv[0] - 2.f * lo0, aqv[1] - 2.f * hi0,
                                aqv[2] - 2.f * lo1, aqv[3] - 2.f * hi1);
        unpack2(acc[i][2], lo0, hi0);
        unpack2(acc[i][3], lo1, hi1);
        float4 o1 = make_float4(aqv[4] - 2.f * lo0, aqv[5] - 2.f * hi0,
                                aqv[6] - 2.f * lo1, aqv[7] - 2.f * hi1);
        float* dst = &g_anti[n * M_ + m0 + tx * 8];
        *(float4*)&dst[0] = o0;
        *(float4*)&dst[4] = o1;
    }
}

// ---------------------------------------------------------------------------
// Kernel 2 (fused): warp-per-row top-6 (lax.top_k semantics: largest values,
// ties -> lowest index), renormalized exp weights over the 6 (full softmax
// denominator cancels), output row, per-row co partial, and a deterministic
// last-block tree reduction for co_loss.
// ---------------------------------------------------------------------------
__global__ void __launch_bounds__(256)
topk_kernel(const float* __restrict__ micro,
            const float* __restrict__ micro_all,
            const float* __restrict__ label,
            const float* __restrict__ label_all,
            float* __restrict__ out, int out_size) {
    const int lane = threadIdx.x & 31;
    const int warp = threadIdx.x >> 5;
    const int n = blockIdx.x * 8 + warp;

    // row into registers: v[j] <-> global index j*32 + lane
    const float* row = &g_anti[n * M_];
    float v[M_ / 32];
    #pragma unroll
    for (int j = 0; j < M_ / 32; j++) v[j] = row[j * 32 + lane];

    float selv[KTOP];
    int   seli[KTOP];
    #pragma unroll
    for (int it = 0; it < KTOP; it++) {
        float best = -INFINITY;
        int   bi   = 0x7fffffff;
        #pragma unroll
        for (int j = 0; j < M_ / 32; j++) {
            if (v[j] > best) { best = v[j]; bi = j * 32 + lane; }  // ascending idx: strict > keeps lowest
        }
        #pragma unroll
        for (int s = 16; s; s >>= 1) {
            float ov = __shfl_xor_sync(0xffffffffu, best, s);
            int   oi = __shfl_xor_sync(0xffffffffu, bi, s);
            if (ov > best || (ov == best && oi < bi)) { best = ov; bi = oi; }
        }
        selv[it] = best;
        seli[it] = bi;
        if ((bi & 31) == lane) {            // owner removes the winner
            int jj = bi >> 5;
            #pragma unroll
            for (int j = 0; j < M_ / 32; j++)
                if (j == jj) v[j] = -INFINITY;
        }
    }

    // exp weights over top-6 (selv[0] is the row max)
    float e[KTOP], s = 0.f;
    #pragma unroll
    for (int k = 0; k < KTOP; k++) { e[k] = expf(selv[k] - selv[0]); s += e[k]; }
    const float inv = 1.f / s;

    if (lane == 0) {
        float lab = label[n];
        float co = 0.f;
        #pragma unroll
        for (int k = 0; k < KTOP; k++)
            co += (e[k] * inv) * fabsf(label_all[seli[k]] - lab);
        g_rowco[n] = co;
    }

    // micro_tmp[n, :] = micro[n, :] + sum_k cut_k * micro_all[idx_k, :]
    const float* mi = &micro[n * C_];
    float* op = &out[n * C_];
    #pragma unroll
    for (int jj = 0; jj < C_ / 32; jj++) {
        int c = lane + jj * 32;
        float o = mi[c];
        #pragma unroll
        for (int k = 0; k < KTOP; k++)
            o += (e[k] * inv) * micro_all[seli[k] * C_ + c];
        op[c] = o;
    }

    // deterministic co_loss: last arriving block does a fixed-order tree
    __threadfence();
    __syncthreads();
    __shared__ int isLast;
    if (threadIdx.x == 0)
        isLast = (atomicAdd(&g_cnt, 1) == (int)gridDim.x - 1);
    __syncthreads();
    if (isLast) {
        __shared__ float red[256];
        red[threadIdx.x] = g_rowco[threadIdx.x] + g_rowco[threadIdx.x + 256];
        __syncthreads();
        #pragma unroll
        for (int s2 = 128; s2 > 0; s2 >>= 1) {
            if (threadIdx.x < s2) red[threadIdx.x] += red[threadIdx.x + s2];
            __syncthreads();
        }
        if (threadIdx.x == 0) {
            if (out_size > N_ * C_)
                out[N_ * C_] = 1e-4f + red[0] / (float)N_;
            g_cnt = 0;   // reset for next launch / graph replay
        }
    }
}

// ---------------------------------------------------------------------------
extern "C" void kernel_launch(void* const* d_in, const int* in_sizes, int n_in,
                              void* d_out, int out_size) {
    const float* micro     = (const float*)d_in[0];   // [512, 256]
    const float* label     = (const float*)d_in[1];   // [512]
    const float* micro_all = (const float*)d_in[2];   // [2048, 256]
    const float* label_all = (const float*)d_in[3];   // [2048]
    const float* fc_w      = (const float*)d_in[4];   // [256]
    float* out = (float*)d_out;

    anti_gemm<<<dim3(M_ / TM, N_ / TN), 128>>>(micro, micro_all, fc_w);
    topk_kernel<<<N_ / 8, 256>>>(micro, micro_all, label, label_all, out, out_size);
}